// round 1
// baseline (speedup 1.0000x reference)
#include <cuda_runtime.h>
#include <math.h>
#include <stdint.h>

// ---------------- problem constants ----------------
#define Bb      2
#define Ll      4096
#define DMODEL  1024
#define DINNER  2048
#define NHEADS  32
#define HEADDIM 64
#define DSTATE  128
#define DCONV   4
#define DIP     4384      // 2*DINNER + 2*DSTATE + NHEADS
#define CONVDIM 2304      // DINNER + 2*DSTATE
#define BL      (Bb*Ll)   // 8192
#define DOUT    1024

// ---------------- device scratch (no allocations allowed) ----------------
__device__ float g_zx [(size_t)BL * DIP];      // in_proj output  (143.6 MB)
__device__ float g_xbc[(size_t)BL * CONVDIM];  // conv+silu out   (75.5 MB)
__device__ float g_y  [(size_t)BL * DINNER];   // scan out / normed (67 MB)
__device__ float g_dt [BL * NHEADS];
__device__ float g_dA [BL * NHEADS];

// =====================================================================
// GEMM (NT): C[M,N] = A[M,K] * B[N,K]^T   (both row-major, K contiguous)
// 128x128 block tile, BK=16, 256 threads, 8x8 per thread.
// N may be non-multiple of 128 (guards on B loads / C stores).
// =====================================================================
__global__ __launch_bounds__(256) void gemm_nt_kernel(
    const float* __restrict__ A, const float* __restrict__ Bw,
    float* __restrict__ C, int M, int N, int K)
{
    const int BM = 128, BN = 128, BK = 16;
    __shared__ float As[BK][BM + 4];
    __shared__ float Bs[BK][BN + 4];

    const int tid = threadIdx.x;
    const int bm = blockIdx.y * BM;
    const int bn = blockIdx.x * BN;
    const int tx = tid & 15;       // 16 cols of threads
    const int ty = tid >> 4;       // 16 rows of threads

    float acc[8][8];
#pragma unroll
    for (int i = 0; i < 8; i++)
#pragma unroll
        for (int j = 0; j < 8; j++) acc[i][j] = 0.f;

    const int lr = tid >> 2;           // 0..63
    const int lc = (tid & 3) << 2;     // 0,4,8,12

    for (int k0 = 0; k0 < K; k0 += BK) {
#pragma unroll
        for (int r = 0; r < 2; r++) {
            const int row = lr + r * 64;
            // A tile (always in-bounds: M multiple of 128)
            float4 av = *(const float4*)(A + (size_t)(bm + row) * K + k0 + lc);
            As[lc + 0][row] = av.x;
            As[lc + 1][row] = av.y;
            As[lc + 2][row] = av.z;
            As[lc + 3][row] = av.w;
            // B tile (guard rows >= N)
            float4 bv = make_float4(0.f, 0.f, 0.f, 0.f);
            const int brow = bn + row;
            if (brow < N)
                bv = *(const float4*)(Bw + (size_t)brow * K + k0 + lc);
            Bs[lc + 0][row] = bv.x;
            Bs[lc + 1][row] = bv.y;
            Bs[lc + 2][row] = bv.z;
            Bs[lc + 3][row] = bv.w;
        }
        __syncthreads();

#pragma unroll
        for (int kk = 0; kk < BK; kk++) {
            float a[8], b[8];
            *(float4*)&a[0] = *(const float4*)&As[kk][ty * 8];
            *(float4*)&a[4] = *(const float4*)&As[kk][ty * 8 + 4];
            *(float4*)&b[0] = *(const float4*)&Bs[kk][tx * 8];
            *(float4*)&b[4] = *(const float4*)&Bs[kk][tx * 8 + 4];
#pragma unroll
            for (int i = 0; i < 8; i++)
#pragma unroll
                for (int j = 0; j < 8; j++)
                    acc[i][j] = fmaf(a[i], b[j], acc[i][j]);
        }
        __syncthreads();
    }

#pragma unroll
    for (int i = 0; i < 8; i++) {
        const int row = bm + ty * 8 + i;
#pragma unroll
        for (int j = 0; j < 8; j++) {
            const int col = bn + tx * 8 + j;
            if (col < N) C[(size_t)row * N + col] = acc[i][j];
        }
    }
}

// =====================================================================
// Depthwise causal conv (taps=4) + bias + SiLU over CONVDIM channels
// =====================================================================
__global__ __launch_bounds__(256) void conv_silu_kernel(
    const float* __restrict__ conv_w, const float* __restrict__ conv_b)
{
    const int idx = blockIdx.x * blockDim.x + threadIdx.x;
    const int total = BL * CONVDIM;
    if (idx >= total) return;
    const int c  = idx % CONVDIM;
    const int bl = idx / CONVDIM;
    const int l  = bl & (Ll - 1);

    float acc = conv_b[c];
    const float* col = g_zx + (size_t)bl * DIP + DINNER + c;
#pragma unroll
    for (int j = 0; j < 4; j++) {
        const int ls = l - 3 + j;
        if (ls >= 0)
            acc = fmaf(col[(long)(j - 3) * DIP], conv_w[c * 4 + j], acc);
    }
    // silu
    g_xbc[idx] = acc / (1.f + expf(-acc));
}

// =====================================================================
// dt: softplus(dt_raw + bias); dA = exp(dt * (-exp(A_log)))
// =====================================================================
__global__ __launch_bounds__(256) void dt_kernel(
    const float* __restrict__ dt_bias, const float* __restrict__ A_log)
{
    const int idx = blockIdx.x * blockDim.x + threadIdx.x;
    if (idx >= BL * NHEADS) return;
    const int h  = idx & (NHEADS - 1);
    const int bl = idx >> 5;
    float raw = g_zx[(size_t)bl * DIP + DINNER + CONVDIM + h] + dt_bias[h];
    float dt = (raw > 20.f) ? raw : log1pf(expf(raw));
    float A = -expf(A_log[h]);
    g_dt[idx] = dt;
    g_dA[idx] = expf(dt * A);
}

// =====================================================================
// Sequential selective scan. One block per (b,h): 64 blocks, 256 threads.
// Thread (p = tid>>2, ns = tid&3) holds 32 states h[p, ns*32 .. ns*32+31].
// Double-buffered smem for B/C/x of step t, register prefetch for dt/dA.
// =====================================================================
__global__ __launch_bounds__(256) void scan_kernel(const float* __restrict__ Dp)
{
    const int bh = blockIdx.x;
    const int b = bh >> 5;
    const int h = bh & 31;
    const int tid = threadIdx.x;
    const int p = tid >> 2;
    const int ns = tid & 3;

    __shared__ float s_bc[2][256];
    __shared__ float s_x[2][64];

    float hs[32];
#pragma unroll
    for (int i = 0; i < 32; i++) hs[i] = 0.f;

    const float* base = g_xbc + (size_t)b * Ll * CONVDIM;
    const float Dh = Dp[h];

    // preload t = 0
    s_bc[0][tid] = base[DINNER + tid];
    if (tid < 64) s_x[0][tid] = base[h * 64 + tid];
    __syncthreads();

    const float* dtp = g_dt + (size_t)b * Ll * NHEADS + h;
    const float* dAp = g_dA + (size_t)b * Ll * NHEADS + h;
    float* yrow = g_y + (size_t)b * Ll * DINNER + h * 64 + p;

    float cdt = dtp[0];
    float cdA = dAp[0];

    for (int t = 0; t < Ll; t++) {
        const int cur = t & 1;
        const int nxt = cur ^ 1;

        // prefetch step t+1 (global -> registers)
        float pf_bc = 0.f, pf_x = 0.f, ndt = 0.f, ndA = 0.f;
        if (t + 1 < Ll) {
            const float* row = base + (size_t)(t + 1) * CONVDIM;
            pf_bc = row[DINNER + tid];
            if (tid < 64) pf_x = row[h * 64 + tid];
            ndt = dtp[(size_t)(t + 1) * NHEADS];
            ndA = dAp[(size_t)(t + 1) * NHEADS];
        }

        const float xp = s_x[cur][p];
        const float kx = cdt * xp;
        const float* Bp = &s_bc[cur][ns * 32];
        const float* Cp = &s_bc[cur][128 + ns * 32];

        float acc = 0.f;
#pragma unroll
        for (int jj = 0; jj < 8; jj++) {
            float4 Bv = *(const float4*)(Bp + jj * 4);
            float4 Cv = *(const float4*)(Cp + jj * 4);
            float h0, h1, h2, h3;
            h0 = fmaf(hs[jj*4+0], cdA, kx * Bv.x); hs[jj*4+0] = h0; acc = fmaf(h0, Cv.x, acc);
            h1 = fmaf(hs[jj*4+1], cdA, kx * Bv.y); hs[jj*4+1] = h1; acc = fmaf(h1, Cv.y, acc);
            h2 = fmaf(hs[jj*4+2], cdA, kx * Bv.z); hs[jj*4+2] = h2; acc = fmaf(h2, Cv.z, acc);
            h3 = fmaf(hs[jj*4+3], cdA, kx * Bv.w); hs[jj*4+3] = h3; acc = fmaf(h3, Cv.w, acc);
        }
        // reduce over the 4 ns lanes sharing this p
        acc += __shfl_xor_sync(0xffffffffu, acc, 1);
        acc += __shfl_xor_sync(0xffffffffu, acc, 2);
        if (ns == 0)
            yrow[(size_t)t * DINNER] = acc + Dh * xp;

        // stage prefetch into the other buffer (safe: its readers finished
        // at the barrier ending iteration t-1), then publish.
        if (t + 1 < Ll) {
            s_bc[nxt][tid] = pf_bc;
            if (tid < 64) s_x[nxt][tid] = pf_x;
        }
        cdt = ndt;
        cdA = ndA;
        __syncthreads();
    }
}

// =====================================================================
// y = y * silu(z);  y *= rsqrt(mean(y^2)+eps) * norm_w   (row = 2048)
// =====================================================================
__global__ __launch_bounds__(256) void gatenorm_kernel(const float* __restrict__ norm_w)
{
    const int row = blockIdx.x;
    const float* zrow = g_zx + (size_t)row * DIP;
    float* yrow = g_y + (size_t)row * DINNER;

    float v[8];
    float ss = 0.f;
#pragma unroll
    for (int i = 0; i < 8; i++) {
        const int c = threadIdx.x + i * 256;
        float d = yrow[c];
        float z = zrow[c];
        float g = d * (z / (1.f + expf(-z)));
        v[i] = g;
        ss = fmaf(g, g, ss);
    }
#pragma unroll
    for (int o = 16; o; o >>= 1) ss += __shfl_xor_sync(0xffffffffu, ss, o);

    __shared__ float red[8];
    if ((threadIdx.x & 31) == 0) red[threadIdx.x >> 5] = ss;
    __syncthreads();
    float tot = 0.f;
#pragma unroll
    for (int w = 0; w < 8; w++) tot += red[w];
    const float scale = rsqrtf(tot * (1.f / (float)DINNER) + 1e-5f);

#pragma unroll
    for (int i = 0; i < 8; i++) {
        const int c = threadIdx.x + i * 256;
        yrow[c] = v[i] * scale * norm_w[c];
    }
}

// =====================================================================
// launch
// =====================================================================
extern "C" void kernel_launch(void* const* d_in, const int* in_sizes, int n_in,
                              void* d_out, int out_size)
{
    const float* x          = (const float*)d_in[0];
    const float* in_proj_w  = (const float*)d_in[1];
    const float* conv_w     = (const float*)d_in[2];
    const float* conv_b     = (const float*)d_in[3];
    const float* dt_bias    = (const float*)d_in[4];
    const float* A_log      = (const float*)d_in[5];
    const float* Dp         = (const float*)d_in[6];
    const float* norm_w     = (const float*)d_in[7];
    const float* out_proj_w = (const float*)d_in[8];
    float* out = (float*)d_out;

    float *zx, *yb;
    cudaGetSymbolAddress((void**)&zx, g_zx);
    cudaGetSymbolAddress((void**)&yb, g_y);

    // 1) in_proj GEMM: [8192,1024] x [4384,1024]^T -> g_zx
    {
        dim3 grid((DIP + 127) / 128, BL / 128);
        gemm_nt_kernel<<<grid, 256>>>(x, in_proj_w, zx, BL, DIP, DMODEL);
    }
    // 2) depthwise conv + silu -> g_xbc
    {
        const int total = BL * CONVDIM;
        conv_silu_kernel<<<(total + 255) / 256, 256>>>(conv_w, conv_b);
    }
    // 3) dt softplus + dA
    dt_kernel<<<(BL * NHEADS) / 256, 256>>>(dt_bias, A_log);
    // 4) sequential scan -> g_y
    scan_kernel<<<Bb * NHEADS, 256>>>(Dp);
    // 5) gate + RMSnorm (in place on g_y)
    gatenorm_kernel<<<BL, 256>>>(norm_w);
    // 6) out_proj GEMM: [8192,2048] x [1024,2048]^T -> d_out
    {
        dim3 grid(DOUT / 128, BL / 128);
        gemm_nt_kernel<<<grid, 256>>>(yb, out_proj_w, out, BL, DOUT, DINNER);
    }
}

// round 2
// speedup vs baseline: 1.9295x; 1.9295x over previous
#include <cuda_runtime.h>
#include <math.h>
#include <stdint.h>

// ---------------- problem constants ----------------
#define Bb      2
#define Ll      4096
#define DMODEL  1024
#define DINNER  2048
#define NHEADS  32
#define HEADDIM 64
#define DSTATE  128
#define DCONV   4
#define DIP     4384      // 2*DINNER + 2*DSTATE + NHEADS
#define CONVDIM 2304      // DINNER + 2*DSTATE
#define BL      (Bb*Ll)   // 8192
#define DOUT    1024

// ---------------- device scratch (no allocations allowed) ----------------
__device__ float g_zx [(size_t)BL * DIP];      // in_proj output
__device__ float g_xbc[(size_t)BL * CONVDIM];  // conv+silu out
__device__ float g_y  [(size_t)BL * DINNER];   // scan out / normed
__device__ float g_dt [BL * NHEADS];
__device__ float g_dA [BL * NHEADS];

// =====================================================================
// TF32 tensor-core GEMM (NT): C[M,N] = A[M,K] * B[N,K]^T
// 128x128 tile, BK=16, 256 threads (8 warps, 2x4), warp tile 64x32.
// fp32 gmem -> cvt.rna.tf32 -> smem -> mma.sync.m16n8k8, fp32 accum.
// =====================================================================
#define GBM 128
#define GBN 128
#define GBK 16
#define GSTR (GBK + 4)   // padded smem row stride (conflict-free frag loads)

__device__ __forceinline__ uint32_t f2tf(float f) {
    uint32_t r;
    asm("cvt.rna.tf32.f32 %0, %1;" : "=r"(r) : "f"(f));
    return r;
}

__device__ __forceinline__ void mma_tf32(float c[4], const uint32_t a[4], const uint32_t b[2]) {
    asm volatile(
        "mma.sync.aligned.m16n8k8.row.col.f32.tf32.tf32.f32 "
        "{%0,%1,%2,%3}, {%4,%5,%6,%7}, {%8,%9}, {%0,%1,%2,%3};"
        : "+f"(c[0]), "+f"(c[1]), "+f"(c[2]), "+f"(c[3])
        : "r"(a[0]), "r"(a[1]), "r"(a[2]), "r"(a[3]), "r"(b[0]), "r"(b[1]));
}

__global__ __launch_bounds__(256, 2) void gemm_tf32_kernel(
    const float* __restrict__ A, const float* __restrict__ Bw,
    float* __restrict__ C, int M, int N, int K)
{
    __shared__ uint32_t As[2][GBM * GSTR];
    __shared__ uint32_t Bs[2][GBN * GSTR];

    const int tid  = threadIdx.x;
    const int lane = tid & 31;
    const int warp = tid >> 5;
    const int wm = (warp >> 2) * 64;   // 0 or 64
    const int wn = (warp & 3) * 32;    // 0,32,64,96
    const int bm = blockIdx.y * GBM;
    const int bn = blockIdx.x * GBN;

    const int lrow = tid >> 2;         // 0..63
    const int lcol = (tid & 3) * 4;    // 0,4,8,12

    float acc[4][4][4];
#pragma unroll
    for (int mt = 0; mt < 4; mt++)
#pragma unroll
        for (int nt = 0; nt < 4; nt++)
#pragma unroll
            for (int i = 0; i < 4; i++) acc[mt][nt][i] = 0.f;

    const int KT = K / GBK;
    float4 ra0, ra1, rb0, rb1;

    // ---- tile load helpers (macros keep it register-resident) ----
#define LOAD_TILE(kt) do {                                                    \
        const float* Ap = A + (size_t)(bm + lrow) * K + (kt) * GBK + lcol;    \
        ra0 = *(const float4*)Ap;                                             \
        ra1 = *(const float4*)(Ap + (size_t)64 * K);                          \
        const int br0 = bn + lrow;                                            \
        const float* Bp = Bw + (size_t)br0 * K + (kt) * GBK + lcol;           \
        rb0 = (br0      < N) ? *(const float4*)Bp                  : make_float4(0,0,0,0); \
        rb1 = (br0 + 64 < N) ? *(const float4*)(Bp + (size_t)64*K) : make_float4(0,0,0,0); \
    } while (0)

#define STORE_TILE(bi) do {                                                   \
        uint4 u;                                                              \
        u.x=f2tf(ra0.x); u.y=f2tf(ra0.y); u.z=f2tf(ra0.z); u.w=f2tf(ra0.w);   \
        *(uint4*)&As[bi][lrow * GSTR + lcol] = u;                             \
        u.x=f2tf(ra1.x); u.y=f2tf(ra1.y); u.z=f2tf(ra1.z); u.w=f2tf(ra1.w);   \
        *(uint4*)&As[bi][(lrow + 64) * GSTR + lcol] = u;                      \
        u.x=f2tf(rb0.x); u.y=f2tf(rb0.y); u.z=f2tf(rb0.z); u.w=f2tf(rb0.w);   \
        *(uint4*)&Bs[bi][lrow * GSTR + lcol] = u;                             \
        u.x=f2tf(rb1.x); u.y=f2tf(rb1.y); u.z=f2tf(rb1.z); u.w=f2tf(rb1.w);   \
        *(uint4*)&Bs[bi][(lrow + 64) * GSTR + lcol] = u;                      \
    } while (0)

    LOAD_TILE(0);
    STORE_TILE(0);
    __syncthreads();

    for (int kt = 0; kt < KT; kt++) {
        const int cur = kt & 1;
        const bool more = (kt + 1 < KT);
        if (more) LOAD_TILE(kt + 1);

#pragma unroll
        for (int ks = 0; ks < 2; ks++) {
            const int k = ks * 8 + (lane & 3);
            uint32_t af[4][4];
#pragma unroll
            for (int mt = 0; mt < 4; mt++) {
                const int m = wm + mt * 16 + (lane >> 2);
                af[mt][0] = As[cur][m       * GSTR + k];
                af[mt][1] = As[cur][(m + 8) * GSTR + k];
                af[mt][2] = As[cur][m       * GSTR + k + 4];
                af[mt][3] = As[cur][(m + 8) * GSTR + k + 4];
            }
            uint32_t bf[4][2];
#pragma unroll
            for (int nt = 0; nt < 4; nt++) {
                const int n = wn + nt * 8 + (lane >> 2);
                bf[nt][0] = Bs[cur][n * GSTR + k];
                bf[nt][1] = Bs[cur][n * GSTR + k + 4];
            }
#pragma unroll
            for (int mt = 0; mt < 4; mt++)
#pragma unroll
                for (int nt = 0; nt < 4; nt++)
                    mma_tf32(acc[mt][nt], af[mt], bf[nt]);
        }

        if (more) STORE_TILE(cur ^ 1);
        __syncthreads();
    }

    // epilogue
#pragma unroll
    for (int mt = 0; mt < 4; mt++) {
        const int row = bm + wm + mt * 16 + (lane >> 2);
#pragma unroll
        for (int nt = 0; nt < 4; nt++) {
            const int col = bn + wn + nt * 8 + (lane & 3) * 2;
            if (col < N) {
                *(float2*)&C[(size_t)row * N + col]       = make_float2(acc[mt][nt][0], acc[mt][nt][1]);
                *(float2*)&C[(size_t)(row + 8) * N + col] = make_float2(acc[mt][nt][2], acc[mt][nt][3]);
            }
        }
    }
#undef LOAD_TILE
#undef STORE_TILE
}

// =====================================================================
// Depthwise causal conv (taps=4) + bias + SiLU over CONVDIM channels
// =====================================================================
__global__ __launch_bounds__(256) void conv_silu_kernel(
    const float* __restrict__ conv_w, const float* __restrict__ conv_b)
{
    const int idx = blockIdx.x * blockDim.x + threadIdx.x;
    const int total = BL * CONVDIM;
    if (idx >= total) return;
    const int c  = idx % CONVDIM;
    const int bl = idx / CONVDIM;
    const int l  = bl & (Ll - 1);

    float acc = conv_b[c];
    const float* col = g_zx + (size_t)bl * DIP + DINNER + c;
#pragma unroll
    for (int j = 0; j < 4; j++) {
        const int ls = l - 3 + j;
        if (ls >= 0)
            acc = fmaf(col[(long)(j - 3) * DIP], conv_w[c * 4 + j], acc);
    }
    g_xbc[idx] = acc / (1.f + expf(-acc));
}

// =====================================================================
// dt: softplus(dt_raw + bias); dA = exp(dt * (-exp(A_log)))
// =====================================================================
__global__ __launch_bounds__(256) void dt_kernel(
    const float* __restrict__ dt_bias, const float* __restrict__ A_log)
{
    const int idx = blockIdx.x * blockDim.x + threadIdx.x;
    if (idx >= BL * NHEADS) return;
    const int h  = idx & (NHEADS - 1);
    const int bl = idx >> 5;
    float raw = g_zx[(size_t)bl * DIP + DINNER + CONVDIM + h] + dt_bias[h];
    float dt = (raw > 20.f) ? raw : log1pf(expf(raw));
    float A = -expf(A_log[h]);
    g_dt[idx] = dt;
    g_dA[idx] = expf(dt * A);
}

// =====================================================================
// Sequential selective scan, split over HEADDIM halves.
// Block = (b, h, phalf): 128 blocks, 256 threads.
// Thread (p = tid>>3 in [0,32), ns = tid&7) holds 16 states.
// y[p] depends only on h[p,:] -> p-split needs no cross-block reduction.
// =====================================================================
__global__ __launch_bounds__(256) void scan_kernel(const float* __restrict__ Dp)
{
    const int bx = blockIdx.x;
    const int bh = bx >> 1;
    const int ph = bx & 1;
    const int b = bh >> 5;
    const int h = bh & 31;
    const int tid = threadIdx.x;
    const int p  = tid >> 3;     // 0..31
    const int ns = tid & 7;      // 0..7 (16 states each)

    __shared__ float s_bc[2][256];
    __shared__ float s_x[2][32];

    float hs[16];
#pragma unroll
    for (int i = 0; i < 16; i++) hs[i] = 0.f;

    const float* base = g_xbc + (size_t)b * Ll * CONVDIM;
    const float Dh = Dp[h];
    const int xoff = h * 64 + ph * 32;

    // preload t = 0
    s_bc[0][tid] = base[DINNER + tid];
    if (tid < 32) s_x[0][tid] = base[xoff + tid];
    __syncthreads();

    const float* dtp = g_dt + (size_t)b * Ll * NHEADS + h;
    const float* dAp = g_dA + (size_t)b * Ll * NHEADS + h;
    float* yrow = g_y + (size_t)b * Ll * DINNER + xoff + p;

    float cdt = dtp[0];
    float cdA = dAp[0];

    for (int t = 0; t < Ll; t++) {
        const int cur = t & 1;
        const int nxt = cur ^ 1;

        // prefetch step t+1 (global -> registers)
        float pf_bc = 0.f, pf_x = 0.f, ndt = 0.f, ndA = 0.f;
        if (t + 1 < Ll) {
            const float* row = base + (size_t)(t + 1) * CONVDIM;
            pf_bc = row[DINNER + tid];
            if (tid < 32) pf_x = row[xoff + tid];
            ndt = dtp[(size_t)(t + 1) * NHEADS];
            ndA = dAp[(size_t)(t + 1) * NHEADS];
        }

        const float xp = s_x[cur][p];
        const float kx = cdt * xp;
        const float* Bp = &s_bc[cur][ns * 16];
        const float* Cp = &s_bc[cur][128 + ns * 16];

        float acc = 0.f;
#pragma unroll
        for (int jj = 0; jj < 4; jj++) {
            float4 Bv = *(const float4*)(Bp + jj * 4);
            float4 Cv = *(const float4*)(Cp + jj * 4);
            float h0, h1, h2, h3;
            h0 = fmaf(hs[jj*4+0], cdA, kx * Bv.x); hs[jj*4+0] = h0; acc = fmaf(h0, Cv.x, acc);
            h1 = fmaf(hs[jj*4+1], cdA, kx * Bv.y); hs[jj*4+1] = h1; acc = fmaf(h1, Cv.y, acc);
            h2 = fmaf(hs[jj*4+2], cdA, kx * Bv.z); hs[jj*4+2] = h2; acc = fmaf(h2, Cv.z, acc);
            h3 = fmaf(hs[jj*4+3], cdA, kx * Bv.w); hs[jj*4+3] = h3; acc = fmaf(h3, Cv.w, acc);
        }
        // reduce over the 8 ns lanes sharing this p (consecutive lanes)
        acc += __shfl_xor_sync(0xffffffffu, acc, 1);
        acc += __shfl_xor_sync(0xffffffffu, acc, 2);
        acc += __shfl_xor_sync(0xffffffffu, acc, 4);
        if (ns == 0)
            yrow[(size_t)t * DINNER] = acc + Dh * xp;

        if (t + 1 < Ll) {
            s_bc[nxt][tid] = pf_bc;
            if (tid < 32) s_x[nxt][tid] = pf_x;
        }
        cdt = ndt;
        cdA = ndA;
        __syncthreads();
    }
}

// =====================================================================
// y = y * silu(z);  y *= rsqrt(mean(y^2)+eps) * norm_w   (row = 2048)
// =====================================================================
__global__ __launch_bounds__(256) void gatenorm_kernel(const float* __restrict__ norm_w)
{
    const int row = blockIdx.x;
    const float* zrow = g_zx + (size_t)row * DIP;
    float* yrow = g_y + (size_t)row * DINNER;

    float v[8];
    float ss = 0.f;
#pragma unroll
    for (int i = 0; i < 8; i++) {
        const int c = threadIdx.x + i * 256;
        float d = yrow[c];
        float z = zrow[c];
        float g = d * (z / (1.f + expf(-z)));
        v[i] = g;
        ss = fmaf(g, g, ss);
    }
#pragma unroll
    for (int o = 16; o; o >>= 1) ss += __shfl_xor_sync(0xffffffffu, ss, o);

    __shared__ float red[8];
    if ((threadIdx.x & 31) == 0) red[threadIdx.x >> 5] = ss;
    __syncthreads();
    float tot = 0.f;
#pragma unroll
    for (int w = 0; w < 8; w++) tot += red[w];
    const float scale = rsqrtf(tot * (1.f / (float)DINNER) + 1e-5f);

#pragma unroll
    for (int i = 0; i < 8; i++) {
        const int c = threadIdx.x + i * 256;
        yrow[c] = v[i] * scale * norm_w[c];
    }
}

// =====================================================================
// launch
// =====================================================================
extern "C" void kernel_launch(void* const* d_in, const int* in_sizes, int n_in,
                              void* d_out, int out_size)
{
    const float* x          = (const float*)d_in[0];
    const float* in_proj_w  = (const float*)d_in[1];
    const float* conv_w     = (const float*)d_in[2];
    const float* conv_b     = (const float*)d_in[3];
    const float* dt_bias    = (const float*)d_in[4];
    const float* A_log      = (const float*)d_in[5];
    const float* Dp         = (const float*)d_in[6];
    const float* norm_w     = (const float*)d_in[7];
    const float* out_proj_w = (const float*)d_in[8];
    float* out = (float*)d_out;

    float *zx, *yb;
    cudaGetSymbolAddress((void**)&zx, g_zx);
    cudaGetSymbolAddress((void**)&yb, g_y);

    // 1) in_proj GEMM: [8192,1024] x [4384,1024]^T -> g_zx
    {
        dim3 grid((DIP + GBN - 1) / GBN, BL / GBM);
        gemm_tf32_kernel<<<grid, 256>>>(x, in_proj_w, zx, BL, DIP, DMODEL);
    }
    // 2) depthwise conv + silu -> g_xbc
    {
        const int total = BL * CONVDIM;
        conv_silu_kernel<<<(total + 255) / 256, 256>>>(conv_w, conv_b);
    }
    // 3) dt softplus + dA
    dt_kernel<<<(BL * NHEADS) / 256, 256>>>(dt_bias, A_log);
    // 4) sequential scan -> g_y (128 blocks: (b,h) x headdim-half)
    scan_kernel<<<2 * Bb * NHEADS, 256>>>(Dp);
    // 5) gate + RMSnorm (in place on g_y)
    gatenorm_kernel<<<BL, 256>>>(norm_w);
    // 6) out_proj GEMM: [8192,2048] x [1024,2048]^T -> d_out
    {
        dim3 grid(DOUT / GBN, BL / GBM);
        gemm_tf32_kernel<<<grid, 256>>>(yb, out_proj_w, out, BL, DOUT, DINNER);
    }
}

// round 3
// speedup vs baseline: 2.7219x; 1.4107x over previous
#include <cuda_runtime.h>
#include <math.h>
#include <stdint.h>

// ---------------- problem constants ----------------
#define Bb      2
#define Ll      4096
#define DMODEL  1024
#define DINNER  2048
#define NHEADS  32
#define HEADDIM 64
#define DSTATE  128
#define DCONV   4
#define DIP     4384      // 2*DINNER + 2*DSTATE + NHEADS
#define CONVDIM 2304      // DINNER + 2*DSTATE
#define BL      (Bb*Ll)   // 8192
#define DOUT    1024

// ---------------- device scratch (no allocations allowed) ----------------
__device__ float g_zx [(size_t)BL * DIP];      // in_proj output
__device__ float g_xbc[(size_t)BL * CONVDIM];  // conv+silu out
__device__ float g_y  [(size_t)BL * DINNER];   // scan out / normed
__device__ float g_dt [BL * NHEADS];
__device__ float g_dA [BL * NHEADS];

// =====================================================================
// TF32 tensor-core GEMM (NT): C[M,N] = A[M,K] * B[N,K]^T
// 128x128 tile, BK=16, 256 threads (8 warps, 2x4), warp tile 64x32.
// fp32 gmem -> cvt.rna.tf32 -> smem -> mma.sync.m16n8k8, fp32 accum.
// =====================================================================
#define GBM 128
#define GBN 128
#define GBK 16
#define GSTR (GBK + 4)   // padded smem row stride

__device__ __forceinline__ uint32_t f2tf(float f) {
    uint32_t r;
    asm("cvt.rna.tf32.f32 %0, %1;" : "=r"(r) : "f"(f));
    return r;
}

__device__ __forceinline__ void mma_tf32(float c[4], const uint32_t a[4], const uint32_t b[2]) {
    asm volatile(
        "mma.sync.aligned.m16n8k8.row.col.f32.tf32.tf32.f32 "
        "{%0,%1,%2,%3}, {%4,%5,%6,%7}, {%8,%9}, {%0,%1,%2,%3};"
        : "+f"(c[0]), "+f"(c[1]), "+f"(c[2]), "+f"(c[3])
        : "r"(a[0]), "r"(a[1]), "r"(a[2]), "r"(a[3]), "r"(b[0]), "r"(b[1]));
}

__global__ __launch_bounds__(256, 2) void gemm_tf32_kernel(
    const float* __restrict__ A, const float* __restrict__ Bw,
    float* __restrict__ C, int M, int N, int K)
{
    __shared__ uint32_t As[2][GBM * GSTR];
    __shared__ uint32_t Bs[2][GBN * GSTR];

    const int tid  = threadIdx.x;
    const int lane = tid & 31;
    const int warp = tid >> 5;
    const int wm = (warp >> 2) * 64;
    const int wn = (warp & 3) * 32;
    const int bm = blockIdx.y * GBM;
    const int bn = blockIdx.x * GBN;

    const int lrow = tid >> 2;
    const int lcol = (tid & 3) * 4;

    float acc[4][4][4];
#pragma unroll
    for (int mt = 0; mt < 4; mt++)
#pragma unroll
        for (int nt = 0; nt < 4; nt++)
#pragma unroll
            for (int i = 0; i < 4; i++) acc[mt][nt][i] = 0.f;

    const int KT = K / GBK;
    float4 ra0, ra1, rb0, rb1;

#define LOAD_TILE(kt) do {                                                    \
        const float* Ap = A + (size_t)(bm + lrow) * K + (kt) * GBK + lcol;    \
        ra0 = *(const float4*)Ap;                                             \
        ra1 = *(const float4*)(Ap + (size_t)64 * K);                          \
        const int br0 = bn + lrow;                                            \
        const float* Bp = Bw + (size_t)br0 * K + (kt) * GBK + lcol;           \
        rb0 = (br0      < N) ? *(const float4*)Bp                  : make_float4(0,0,0,0); \
        rb1 = (br0 + 64 < N) ? *(const float4*)(Bp + (size_t)64*K) : make_float4(0,0,0,0); \
    } while (0)

#define STORE_TILE(bi) do {                                                   \
        uint4 u;                                                              \
        u.x=f2tf(ra0.x); u.y=f2tf(ra0.y); u.z=f2tf(ra0.z); u.w=f2tf(ra0.w);   \
        *(uint4*)&As[bi][lrow * GSTR + lcol] = u;                             \
        u.x=f2tf(ra1.x); u.y=f2tf(ra1.y); u.z=f2tf(ra1.z); u.w=f2tf(ra1.w);   \
        *(uint4*)&As[bi][(lrow + 64) * GSTR + lcol] = u;                      \
        u.x=f2tf(rb0.x); u.y=f2tf(rb0.y); u.z=f2tf(rb0.z); u.w=f2tf(rb0.w);   \
        *(uint4*)&Bs[bi][lrow * GSTR + lcol] = u;                             \
        u.x=f2tf(rb1.x); u.y=f2tf(rb1.y); u.z=f2tf(rb1.z); u.w=f2tf(rb1.w);   \
        *(uint4*)&Bs[bi][(lrow + 64) * GSTR + lcol] = u;                      \
    } while (0)

    LOAD_TILE(0);
    STORE_TILE(0);
    __syncthreads();

    for (int kt = 0; kt < KT; kt++) {
        const int cur = kt & 1;
        const bool more = (kt + 1 < KT);
        if (more) LOAD_TILE(kt + 1);

#pragma unroll
        for (int ks = 0; ks < 2; ks++) {
            const int k = ks * 8 + (lane & 3);
            uint32_t af[4][4];
#pragma unroll
            for (int mt = 0; mt < 4; mt++) {
                const int m = wm + mt * 16 + (lane >> 2);
                af[mt][0] = As[cur][m       * GSTR + k];
                af[mt][1] = As[cur][(m + 8) * GSTR + k];
                af[mt][2] = As[cur][m       * GSTR + k + 4];
                af[mt][3] = As[cur][(m + 8) * GSTR + k + 4];
            }
            uint32_t bf[4][2];
#pragma unroll
            for (int nt = 0; nt < 4; nt++) {
                const int n = wn + nt * 8 + (lane >> 2);
                bf[nt][0] = Bs[cur][n * GSTR + k];
                bf[nt][1] = Bs[cur][n * GSTR + k + 4];
            }
#pragma unroll
            for (int mt = 0; mt < 4; mt++)
#pragma unroll
                for (int nt = 0; nt < 4; nt++)
                    mma_tf32(acc[mt][nt], af[mt], bf[nt]);
        }

        if (more) STORE_TILE(cur ^ 1);
        __syncthreads();
    }

#pragma unroll
    for (int mt = 0; mt < 4; mt++) {
        const int row = bm + wm + mt * 16 + (lane >> 2);
#pragma unroll
        for (int nt = 0; nt < 4; nt++) {
            const int col = bn + wn + nt * 8 + (lane & 3) * 2;
            if (col < N) {
                *(float2*)&C[(size_t)row * N + col]       = make_float2(acc[mt][nt][0], acc[mt][nt][1]);
                *(float2*)&C[(size_t)(row + 8) * N + col] = make_float2(acc[mt][nt][2], acc[mt][nt][3]);
            }
        }
    }
#undef LOAD_TILE
#undef STORE_TILE
}

// =====================================================================
// Depthwise causal conv (taps=4) + bias + SiLU over CONVDIM channels
// =====================================================================
__global__ __launch_bounds__(256) void conv_silu_kernel(
    const float* __restrict__ conv_w, const float* __restrict__ conv_b)
{
    const int idx = blockIdx.x * blockDim.x + threadIdx.x;
    const int total = BL * CONVDIM;
    if (idx >= total) return;
    const int c  = idx % CONVDIM;
    const int bl = idx / CONVDIM;
    const int l  = bl & (Ll - 1);

    float acc = conv_b[c];
    const float* col = g_zx + (size_t)bl * DIP + DINNER + c;
#pragma unroll
    for (int j = 0; j < 4; j++) {
        const int ls = l - 3 + j;
        if (ls >= 0)
            acc = fmaf(col[(long)(j - 3) * DIP], conv_w[c * 4 + j], acc);
    }
    g_xbc[idx] = acc / (1.f + expf(-acc));
}

// =====================================================================
// dt: softplus(dt_raw + bias); dA = exp(dt * (-exp(A_log)))
// =====================================================================
__global__ __launch_bounds__(256) void dt_kernel(
    const float* __restrict__ dt_bias, const float* __restrict__ A_log)
{
    const int idx = blockIdx.x * blockDim.x + threadIdx.x;
    if (idx >= BL * NHEADS) return;
    const int h  = idx & (NHEADS - 1);
    const int bl = idx >> 5;
    float raw = g_zx[(size_t)bl * DIP + DINNER + CONVDIM + h] + dt_bias[h];
    float dt = (raw > 20.f) ? raw : log1pf(expf(raw));
    float A = -expf(A_log[h]);
    g_dt[idx] = dt;
    g_dA[idx] = expf(dt * A);
}

// =====================================================================
// Chunked deep-pipelined selective scan.
// Block = (b, h, phalf): 128 blocks, 256 threads.
// Thread (p = tid>>3 in [0,32), ns = tid&7) holds 16 states.
// D=8 steps per chunk; double-buffered smem; loads for chunk i+2 are
// issued at chunk i (load->use distance ~1 full chunk of compute);
// ONE __syncthreads per chunk (1/8 per step).
// =====================================================================
#define DCH 8

__global__ __launch_bounds__(256) void scan_kernel(const float* __restrict__ Dp)
{
    const int bx = blockIdx.x;
    const int bh = bx >> 1;
    const int ph = bx & 1;
    const int b = bh >> 5;
    const int h = bh & 31;
    const int tid = threadIdx.x;
    const int p  = tid >> 3;     // 0..31
    const int ns = tid & 7;      // 0..7

    __shared__ float s_bc[2][DCH][256];
    __shared__ float s_x [2][DCH][32];
    __shared__ float s_dt[2][DCH];
    __shared__ float s_dA[2][DCH];

    float hs[16];
#pragma unroll
    for (int i = 0; i < 16; i++) hs[i] = 0.f;

    const float* base = g_xbc + (size_t)b * Ll * CONVDIM;
    const float* dtp  = g_dt  + (size_t)b * Ll * NHEADS + h;
    const float* dAp  = g_dA  + (size_t)b * Ll * NHEADS + h;
    const float Dh = Dp[h];
    const int xoff = h * 64 + ph * 32;
    float* yrow = g_y + (size_t)b * Ll * DINNER + xoff + p;

    // ---- prologue: chunk 0 straight to smem ----
#pragma unroll
    for (int d = 0; d < DCH; d++)
        s_bc[0][d][tid] = base[(size_t)d * CONVDIM + DINNER + tid];
    if (tid < 32) {
#pragma unroll
        for (int d = 0; d < DCH; d++)
            s_x[0][d][tid] = base[(size_t)d * CONVDIM + xoff + tid];
    }
    if (tid < DCH)               s_dt[0][tid]       = dtp[(size_t)tid * NHEADS];
    else if (tid < 2 * DCH)      s_dA[0][tid - DCH] = dAp[(size_t)(tid - DCH) * NHEADS];

    // ---- prefetch chunk 1 into registers ----
    float pf[DCH], pfx[DCH];
    float pfdt = 0.f, pfdA = 0.f;
#pragma unroll
    for (int d = 0; d < DCH; d++)
        pf[d] = base[(size_t)(DCH + d) * CONVDIM + DINNER + tid];
    if (tid < 32) {
#pragma unroll
        for (int d = 0; d < DCH; d++)
            pfx[d] = base[(size_t)(DCH + d) * CONVDIM + xoff + tid];
    }
    if (tid < DCH)               pfdt = dtp[(size_t)(DCH + tid) * NHEADS];
    else if (tid < 2 * DCH)      pfdA = dAp[(size_t)(DCH + tid - DCH) * NHEADS];
    __syncthreads();

    const int NCH = Ll / DCH;
    int buf = 0;
    for (int ci = 0; ci < NCH; ci++) {
        // 1) publish registers (chunk ci+1) into the idle buffer
        if (ci + 1 < NCH) {
#pragma unroll
            for (int d = 0; d < DCH; d++) s_bc[buf ^ 1][d][tid] = pf[d];
            if (tid < 32) {
#pragma unroll
                for (int d = 0; d < DCH; d++) s_x[buf ^ 1][d][tid] = pfx[d];
            }
            if (tid < DCH)          s_dt[buf ^ 1][tid]       = pfdt;
            else if (tid < 2 * DCH) s_dA[buf ^ 1][tid - DCH] = pfdA;
        }
        // 2) issue loads for chunk ci+2 (consumed next iteration)
        if (ci + 2 < NCH) {
            const size_t t2 = (size_t)(ci + 2) * DCH;
#pragma unroll
            for (int d = 0; d < DCH; d++)
                pf[d] = base[(t2 + d) * CONVDIM + DINNER + tid];
            if (tid < 32) {
#pragma unroll
                for (int d = 0; d < DCH; d++)
                    pfx[d] = base[(t2 + d) * CONVDIM + xoff + tid];
            }
            if (tid < DCH)          pfdt = dtp[(t2 + tid) * NHEADS];
            else if (tid < 2 * DCH) pfdA = dAp[(t2 + tid - DCH) * NHEADS];
        }
        // 3) process DCH steps from the current buffer
        const int t0 = ci * DCH;
#pragma unroll
        for (int d = 0; d < DCH; d++) {
            const float cdt = s_dt[buf][d];
            const float cdA = s_dA[buf][d];
            const float xp  = s_x[buf][d][p];
            const float kx  = cdt * xp;
            const float* Bp = &s_bc[buf][d][ns * 16];
            const float* Cp = &s_bc[buf][d][128 + ns * 16];

            float acc = 0.f;
#pragma unroll
            for (int jj = 0; jj < 4; jj++) {
                float4 Bv = *(const float4*)(Bp + jj * 4);
                float4 Cv = *(const float4*)(Cp + jj * 4);
                float h0, h1, h2, h3;
                h0 = fmaf(hs[jj*4+0], cdA, kx * Bv.x); hs[jj*4+0] = h0; acc = fmaf(h0, Cv.x, acc);
                h1 = fmaf(hs[jj*4+1], cdA, kx * Bv.y); hs[jj*4+1] = h1; acc = fmaf(h1, Cv.y, acc);
                h2 = fmaf(hs[jj*4+2], cdA, kx * Bv.z); hs[jj*4+2] = h2; acc = fmaf(h2, Cv.z, acc);
                h3 = fmaf(hs[jj*4+3], cdA, kx * Bv.w); hs[jj*4+3] = h3; acc = fmaf(h3, Cv.w, acc);
            }
            acc += __shfl_xor_sync(0xffffffffu, acc, 1);
            acc += __shfl_xor_sync(0xffffffffu, acc, 2);
            acc += __shfl_xor_sync(0xffffffffu, acc, 4);
            if (ns == 0)
                yrow[(size_t)(t0 + d) * DINNER] = acc + Dh * xp;
        }
        __syncthreads();
        buf ^= 1;
    }
}

// =====================================================================
// y = y * silu(z);  y *= rsqrt(mean(y^2)+eps) * norm_w   (row = 2048)
// =====================================================================
__global__ __launch_bounds__(256) void gatenorm_kernel(const float* __restrict__ norm_w)
{
    const int row = blockIdx.x;
    const float* zrow = g_zx + (size_t)row * DIP;
    float* yrow = g_y + (size_t)row * DINNER;

    float v[8];
    float ss = 0.f;
#pragma unroll
    for (int i = 0; i < 8; i++) {
        const int c = threadIdx.x + i * 256;
        float d = yrow[c];
        float z = zrow[c];
        float g = d * (z / (1.f + expf(-z)));
        v[i] = g;
        ss = fmaf(g, g, ss);
    }
#pragma unroll
    for (int o = 16; o; o >>= 1) ss += __shfl_xor_sync(0xffffffffu, ss, o);

    __shared__ float red[8];
    if ((threadIdx.x & 31) == 0) red[threadIdx.x >> 5] = ss;
    __syncthreads();
    float tot = 0.f;
#pragma unroll
    for (int w = 0; w < 8; w++) tot += red[w];
    const float scale = rsqrtf(tot * (1.f / (float)DINNER) + 1e-5f);

#pragma unroll
    for (int i = 0; i < 8; i++) {
        const int c = threadIdx.x + i * 256;
        yrow[c] = v[i] * scale * norm_w[c];
    }
}

// =====================================================================
// launch
// =====================================================================
extern "C" void kernel_launch(void* const* d_in, const int* in_sizes, int n_in,
                              void* d_out, int out_size)
{
    const float* x          = (const float*)d_in[0];
    const float* in_proj_w  = (const float*)d_in[1];
    const float* conv_w     = (const float*)d_in[2];
    const float* conv_b     = (const float*)d_in[3];
    const float* dt_bias    = (const float*)d_in[4];
    const float* A_log      = (const float*)d_in[5];
    const float* Dp         = (const float*)d_in[6];
    const float* norm_w     = (const float*)d_in[7];
    const float* out_proj_w = (const float*)d_in[8];
    float* out = (float*)d_out;

    float *zx, *yb;
    cudaGetSymbolAddress((void**)&zx, g_zx);
    cudaGetSymbolAddress((void**)&yb, g_y);

    // 1) in_proj GEMM
    {
        dim3 grid((DIP + GBN - 1) / GBN, BL / GBM);
        gemm_tf32_kernel<<<grid, 256>>>(x, in_proj_w, zx, BL, DIP, DMODEL);
    }
    // 2) depthwise conv + silu
    {
        const int total = BL * CONVDIM;
        conv_silu_kernel<<<(total + 255) / 256, 256>>>(conv_w, conv_b);
    }
    // 3) dt softplus + dA
    dt_kernel<<<(BL * NHEADS) / 256, 256>>>(dt_bias, A_log);
    // 4) chunked pipelined scan
    scan_kernel<<<2 * Bb * NHEADS, 256>>>(Dp);
    // 5) gate + RMSnorm
    gatenorm_kernel<<<BL, 256>>>(norm_w);
    // 6) out_proj GEMM
    {
        dim3 grid(DOUT / GBN, BL / GBM);
        gemm_tf32_kernel<<<grid, 256>>>(yb, out_proj_w, out, BL, DOUT, DINNER);
    }
}